// round 4
// baseline (speedup 1.0000x reference)
#include <cuda_runtime.h>
#include <math.h>

// ---------------------------------------------------------------------------
// Problem constants
// ---------------------------------------------------------------------------
#define N_CLASS   128
#define N_SUPPORT 32
#define N_QUERY   128
#define IN_DIM    2048
#define Z_DIM     1024
#define KCLUST    2

#define NS_ROWS (N_CLASS * N_SUPPORT)   // 4096
#define NQ_ROWS (N_CLASS * N_QUERY)    // 16384
#define NZ_ROWS (NS_ROWS + NQ_ROWS)    // 20480
#define N_PROTO (N_CLASS * KCLUST)     // 256

// ---------------------------------------------------------------------------
// Scratch (device globals; no allocation allowed)
// ---------------------------------------------------------------------------
__device__ float g_z[(size_t)NZ_ROWS * Z_DIM];          // 80 MB
__device__ float g_protosT[(size_t)Z_DIM * N_PROTO];    // 1 MB (K x N layout)
__device__ float g_proto_sq[N_PROTO];
__device__ float g_qnorm[NQ_ROWS];
__device__ float g_dists[(size_t)NQ_ROWS * N_CLASS];    // 8 MB
__device__ float g_lpart[NQ_ROWS];
__device__ float g_apart[NQ_ROWS];

// ---------------------------------------------------------------------------
// GEMM1: C[M,N] = A[M,K] @ B[K,N], fp32, two-level accumulation.
// 128x128 tile, BK=16, 256 threads, 8x8 micro-tile.
// ---------------------------------------------------------------------------
#define BM 128
#define BN 128
#define BK 16
#define TM 8
#define TN 8

__global__ __launch_bounds__(256) void gemm_f32(
    const float* __restrict__ A, const float* __restrict__ B,
    float* __restrict__ C, int M, int N, int K)
{
    __shared__ float As[BK][BM];
    __shared__ float Bs[BK][BN];

    const int bx = blockIdx.x;
    const int by = blockIdx.y;
    const int tid = threadIdx.x;
    const int tx = tid & 15;
    const int ty = tid >> 4;

    const float* Ablk = A + (size_t)by * BM * K;
    const float* Bblk = B + (size_t)bx * BN;

    float acc[TM][TN];
    #pragma unroll
    for (int m = 0; m < TM; m++)
        #pragma unroll
        for (int n = 0; n < TN; n++) acc[m][n] = 0.0f;

    for (int k0 = 0; k0 < K; k0 += BK) {
        #pragma unroll
        for (int i = 0; i < 2; i++) {
            int idx = tid + i * 256;
            int row = idx >> 2;
            int c4  = idx & 3;
            float4 v = *(const float4*)(Ablk + (size_t)row * K + k0 + c4 * 4);
            As[c4 * 4 + 0][row] = v.x;
            As[c4 * 4 + 1][row] = v.y;
            As[c4 * 4 + 2][row] = v.z;
            As[c4 * 4 + 3][row] = v.w;
        }
        #pragma unroll
        for (int i = 0; i < 2; i++) {
            int idx = tid + i * 256;
            int row = idx >> 5;
            int c4  = idx & 31;
            float4 v = *(const float4*)(Bblk + (size_t)(k0 + row) * N + c4 * 4);
            *(float4*)&Bs[row][c4 * 4] = v;
        }
        __syncthreads();

        float part[TM][TN];
        #pragma unroll
        for (int m = 0; m < TM; m++)
            #pragma unroll
            for (int n = 0; n < TN; n++) part[m][n] = 0.0f;

        #pragma unroll
        for (int k = 0; k < BK; k++) {
            float a[TM], b[TN];
            #pragma unroll
            for (int m = 0; m < TM; m++) a[m] = As[k][ty * TM + m];
            #pragma unroll
            for (int n = 0; n < TN; n++) b[n] = Bs[k][tx * TN + n];
            #pragma unroll
            for (int m = 0; m < TM; m++)
                #pragma unroll
                for (int n = 0; n < TN; n++)
                    part[m][n] = fmaf(a[m], b[n], part[m][n]);
        }
        #pragma unroll
        for (int m = 0; m < TM; m++)
            #pragma unroll
            for (int n = 0; n < TN; n++) acc[m][n] += part[m][n];
        __syncthreads();
    }

    float* Cblk = C + (size_t)by * BM * N + (size_t)bx * BN;
    #pragma unroll
    for (int m = 0; m < TM; m++) {
        int row = ty * TM + m;
        #pragma unroll
        for (int n = 0; n < TN; n += 4) {
            float4 v = make_float4(acc[m][n], acc[m][n+1], acc[m][n+2], acc[m][n+3]);
            *(float4*)(Cblk + (size_t)row * N + tx * TN + n) = v;
        }
    }
}

// ---------------------------------------------------------------------------
// Query row norms in fp64, rounded once to fp32.
// ---------------------------------------------------------------------------
__global__ __launch_bounds__(256) void qnorm_kernel(
    const float* __restrict__ zq, float* __restrict__ qn)
{
    int q = blockIdx.x;
    const float* row = zq + (size_t)q * Z_DIM;
    int tid = threadIdx.x;
    double s = 0.0;
    for (int d = tid; d < Z_DIM; d += 256) {
        double v = (double)row[d];
        s = fma(v, v, s);
    }
    __shared__ double red[256];
    red[tid] = s;
    __syncthreads();
    for (int o = 128; o > 0; o >>= 1) {
        if (tid < o) red[tid] += red[tid + o];
        __syncthreads();
    }
    if (tid == 0) qn[q] = (float)red[0];
}

// ---------------------------------------------------------------------------
// Per-class assignment (fp64) + centroids (fp64 sums -> fp32) + proto norms.
// ---------------------------------------------------------------------------
__global__ __launch_bounds__(256) void centroid_kernel(
    const float* __restrict__ z,
    float* __restrict__ protosT,
    float* __restrict__ proto_sq)
{
    int c = blockIdx.x;
    const float* zs = z + (size_t)c * N_SUPPORT * Z_DIM;
    int tid = threadIdx.x;
    int wid = tid >> 5, lane = tid & 31;

    __shared__ double d0s[N_SUPPORT], d1s[N_SUPPORT];
    __shared__ int    sAssign[N_SUPPORT];
    __shared__ int    sCnt0, sCnt1;

    for (int s = wid; s < N_SUPPORT; s += 8) {
        double d0 = 0.0, d1 = 0.0;
        for (int d = lane; d < Z_DIM; d += 32) {
            double v = (double)zs[(size_t)s * Z_DIM + d];
            double a = v - (double)zs[d];
            double b = v - (double)zs[(size_t)Z_DIM + d];
            d0 = fma(a, a, d0);
            d1 = fma(b, b, d1);
        }
        #pragma unroll
        for (int o = 16; o > 0; o >>= 1) {
            d0 += __shfl_down_sync(0xffffffffu, d0, o);
            d1 += __shfl_down_sync(0xffffffffu, d1, o);
        }
        if (lane == 0) { d0s[s] = d0; d1s[s] = d1; }
    }
    __syncthreads();

    if (tid < N_SUPPORT)
        sAssign[tid] = (d1s[tid] < d0s[tid]) ? 1 : 0;
    __syncthreads();

    if (tid == 0) {
        int c1 = 0;
        for (int s = 0; s < N_SUPPORT; s++) c1 += sAssign[s];
        sCnt1 = c1;
        sCnt0 = N_SUPPORT - c1;
    }
    __syncthreads();

    int cnt0 = sCnt0, cnt1 = sCnt1;

    double sq0 = 0.0, sq1 = 0.0;
    for (int d = tid; d < Z_DIM; d += 256) {
        double s0 = 0.0, s1 = 0.0;
        for (int s = 0; s < N_SUPPORT; s++) {
            double v = (double)zs[(size_t)s * Z_DIM + d];
            if (sAssign[s]) s1 += v; else s0 += v;
        }
        float c0f, c1f;
        c0f = (cnt0 > 0) ? (float)(s0 / (double)(cnt0 > 1 ? cnt0 : 1)) : zs[d];
        c1f = (cnt1 > 0) ? (float)(s1 / (double)(cnt1 > 1 ? cnt1 : 1))
                         : zs[(size_t)Z_DIM + d];
        protosT[(size_t)d * N_PROTO + 2 * c]     = c0f;
        protosT[(size_t)d * N_PROTO + 2 * c + 1] = c1f;
        sq0 = fma((double)c0f, (double)c0f, sq0);
        sq1 = fma((double)c1f, (double)c1f, sq1);
    }

    __shared__ double r0[256], r1[256];
    r0[tid] = sq0; r1[tid] = sq1;
    __syncthreads();
    for (int o = 128; o > 0; o >>= 1) {
        if (tid < o) { r0[tid] += r0[tid + o]; r1[tid] += r1[tid + o]; }
        __syncthreads();
    }
    if (tid == 0) {
        proto_sq[2 * c]     = (float)r0[0];
        proto_sq[2 * c + 1] = (float)r1[0];
    }
}

// ---------------------------------------------------------------------------
// GEMM2 + epilogue: d = (qn + pn) - 2*S (fp32 reference rounding sequence);
// clamp 0; min over K=2.
// ---------------------------------------------------------------------------
__global__ __launch_bounds__(256) void dist_gemm_kernel(
    const float* __restrict__ A, const float* __restrict__ B,
    const float* __restrict__ qn, const float* __restrict__ pn,
    float* __restrict__ dists)
{
    const int Nn = N_PROTO;
    const int Kk = Z_DIM;

    __shared__ float As[BK][BM];
    __shared__ float Bs[BK][BN];

    const int bx = blockIdx.x;
    const int by = blockIdx.y;
    const int tid = threadIdx.x;
    const int tx = tid & 15;
    const int ty = tid >> 4;

    const float* Ablk = A + (size_t)by * BM * Kk;
    const float* Bblk = B + (size_t)bx * BN;

    float acc[TM][TN];
    #pragma unroll
    for (int m = 0; m < TM; m++)
        #pragma unroll
        for (int n = 0; n < TN; n++) acc[m][n] = 0.0f;

    for (int k0 = 0; k0 < Kk; k0 += BK) {
        #pragma unroll
        for (int i = 0; i < 2; i++) {
            int idx = tid + i * 256;
            int row = idx >> 2;
            int c4  = idx & 3;
            float4 v = *(const float4*)(Ablk + (size_t)row * Kk + k0 + c4 * 4);
            As[c4 * 4 + 0][row] = v.x;
            As[c4 * 4 + 1][row] = v.y;
            As[c4 * 4 + 2][row] = v.z;
            As[c4 * 4 + 3][row] = v.w;
        }
        #pragma unroll
        for (int i = 0; i < 2; i++) {
            int idx = tid + i * 256;
            int row = idx >> 5;
            int c4  = idx & 31;
            float4 v = *(const float4*)(Bblk + (size_t)(k0 + row) * Nn + c4 * 4);
            *(float4*)&Bs[row][c4 * 4] = v;
        }
        __syncthreads();

        float part[TM][TN];
        #pragma unroll
        for (int m = 0; m < TM; m++)
            #pragma unroll
            for (int n = 0; n < TN; n++) part[m][n] = 0.0f;

        #pragma unroll
        for (int k = 0; k < BK; k++) {
            float a[TM], b[TN];
            #pragma unroll
            for (int m = 0; m < TM; m++) a[m] = As[k][ty * TM + m];
            #pragma unroll
            for (int n = 0; n < TN; n++) b[n] = Bs[k][tx * TN + n];
            #pragma unroll
            for (int m = 0; m < TM; m++)
                #pragma unroll
                for (int n = 0; n < TN; n++)
                    part[m][n] = fmaf(a[m], b[n], part[m][n]);
        }
        #pragma unroll
        for (int m = 0; m < TM; m++)
            #pragma unroll
            for (int n = 0; n < TN; n++) acc[m][n] += part[m][n];
        __syncthreads();
    }

    #pragma unroll
    for (int m = 0; m < TM; m++) {
        int q = by * BM + ty * TM + m;
        float qv = qn[q];
        #pragma unroll
        for (int n = 0; n < TN; n += 2) {
            int gcol = bx * BN + tx * TN + n;
            float t0 = __fadd_rn(qv, pn[gcol]);
            float t1 = __fadd_rn(qv, pn[gcol + 1]);
            float d0 = __fadd_rn(t0, -__fmul_rn(2.0f, acc[m][n]));
            float d1 = __fadd_rn(t1, -__fmul_rn(2.0f, acc[m][n + 1]));
            d0 = fmaxf(d0, 0.0f);
            d1 = fmaxf(d1, 0.0f);
            dists[(size_t)q * N_CLASS + (gcol >> 1)] = fminf(d0, d1);
        }
    }
}

// ---------------------------------------------------------------------------
// Per-query loss + accuracy.
//
// Accuracy emulates the reference's argmax over log(dists/sum): the reference
// computes distances entirely in fp32, so classes whose exact distances differ
// by sub-ulp amounts COLLIDE to equal fp32 values there, and argmax resolves
// by first index. We reproduce that with an epsilon-snapped argmax: among all
// classes within rel eps (~1.5-2 ulp) of the max, pick the smallest index.
// ---------------------------------------------------------------------------
__global__ __launch_bounds__(128) void loss_kernel(
    const float* __restrict__ dists,
    float* __restrict__ lpart, float* __restrict__ apart)
{
    int q = blockIdx.x;
    int c = threadIdx.x;
    float v = dists[(size_t)q * N_CLASS + c];

    __shared__ float sv[128];
    __shared__ float mv[128];
    sv[c] = v; mv[c] = v;
    __syncthreads();

    // sum + max-value reductions
    for (int o = 64; o > 0; o >>= 1) {
        if (c < o) {
            sv[c] += sv[c + o];
            mv[c] = fmaxf(mv[c], mv[c + o]);
        }
        __syncthreads();
    }
    float m = mv[0];
    __syncthreads();

    // epsilon-snapped argmax: smallest index within rel 3e-7 of the max
    __shared__ int ci[128];
    float thresh = fmaf(m, -3e-7f, m);   // m * (1 - 3e-7)
    ci[c] = (v >= thresh) ? c : (N_CLASS + 1);
    __syncthreads();
    for (int o = 64; o > 0; o >>= 1) {
        if (c < o) ci[c] = min(ci[c], ci[c + o]);
        __syncthreads();
    }

    if (c == 0) {
        int ct = q >> 7;
        float vt = dists[(size_t)q * N_CLASS + ct];
        lpart[q] = logf(sv[0]) - logf(vt);
        apart[q] = (ci[0] == ct) ? 1.0f : 0.0f;
    }
}

// ---------------------------------------------------------------------------
// Deterministic final reduction (fp64).
// ---------------------------------------------------------------------------
__global__ __launch_bounds__(256) void final_kernel(
    const float* __restrict__ lpart, const float* __restrict__ apart,
    float* __restrict__ out)
{
    __shared__ double ls[256], as_[256];
    int tid = threadIdx.x;
    double l = 0.0, a = 0.0;
    int base = tid * (NQ_ROWS / 256);
    for (int i = 0; i < NQ_ROWS / 256; i++) {
        l += (double)lpart[base + i];
        a += (double)apart[base + i];
    }
    ls[tid] = l; as_[tid] = a;
    __syncthreads();
    for (int o = 128; o > 0; o >>= 1) {
        if (tid < o) { ls[tid] += ls[tid + o]; as_[tid] += as_[tid + o]; }
        __syncthreads();
    }
    if (tid == 0) {
        out[0] = (float)(ls[0] / (double)NQ_ROWS);
        out[1] = (float)(as_[0] / (double)NQ_ROWS);
    }
}

// ---------------------------------------------------------------------------
// Launch
// ---------------------------------------------------------------------------
extern "C" void kernel_launch(void* const* d_in, const int* in_sizes, int n_in,
                              void* d_out, int out_size)
{
    const float* xs = (const float*)d_in[0];
    const float* xq = (const float*)d_in[1];
    const float* W  = (const float*)d_in[2];
    float* out = (float*)d_out;

    float* z;        cudaGetSymbolAddress((void**)&z, g_z);
    float* protosT;  cudaGetSymbolAddress((void**)&protosT, g_protosT);
    float* proto_sq; cudaGetSymbolAddress((void**)&proto_sq, g_proto_sq);
    float* qnorm;    cudaGetSymbolAddress((void**)&qnorm, g_qnorm);
    float* dists;    cudaGetSymbolAddress((void**)&dists, g_dists);
    float* lpart;    cudaGetSymbolAddress((void**)&lpart, g_lpart);
    float* apart;    cudaGetSymbolAddress((void**)&apart, g_apart);

    float* zq = z + (size_t)NS_ROWS * Z_DIM;

    dim3 gs(Z_DIM / BN, NS_ROWS / BM);
    gemm_f32<<<gs, 256>>>(xs, W, z, NS_ROWS, Z_DIM, IN_DIM);
    dim3 gq(Z_DIM / BN, NQ_ROWS / BM);
    gemm_f32<<<gq, 256>>>(xq, W, zq, NQ_ROWS, Z_DIM, IN_DIM);

    qnorm_kernel<<<NQ_ROWS, 256>>>(zq, qnorm);
    centroid_kernel<<<N_CLASS, 256>>>(z, protosT, proto_sq);

    dim3 gd(N_PROTO / BN, NQ_ROWS / BM);
    dist_gemm_kernel<<<gd, 256>>>(zq, protosT, qnorm, proto_sq, dists);

    loss_kernel<<<NQ_ROWS, 128>>>(dists, lpart, apart);
    final_kernel<<<1, 256>>>(lpart, apart, out);
}

// round 6
// speedup vs baseline: 1.5236x; 1.5236x over previous
#include <cuda_runtime.h>
#include <cuda_bf16.h>
#include <math.h>
#include <stdint.h>

// ---------------------------------------------------------------------------
// Problem constants
// ---------------------------------------------------------------------------
#define N_CLASS   128
#define N_SUPPORT 32
#define N_QUERY   128
#define IN_DIM    2048
#define Z_DIM     1024
#define KCLUST    2

#define NS_ROWS (N_CLASS * N_SUPPORT)   // 4096
#define NQ_ROWS (N_CLASS * N_QUERY)    // 16384
#define NZ_ROWS (NS_ROWS + NQ_ROWS)    // 20480
#define N_PROTO (N_CLASS * KCLUST)     // 256

// ---------------------------------------------------------------------------
// Scratch (device globals; no allocation allowed)
// ---------------------------------------------------------------------------
__device__ float g_z[(size_t)NZ_ROWS * Z_DIM];          // 80 MB
__device__ float g_protosT[(size_t)Z_DIM * N_PROTO];    // 1 MB (K x N layout)
__device__ float g_proto_sq[N_PROTO];
__device__ float g_qnorm[NQ_ROWS];
__device__ float g_dists[(size_t)NQ_ROWS * N_CLASS];    // 8 MB
__device__ float g_lpart[NQ_ROWS];
__device__ float g_apart[NQ_ROWS];

// bf16 splits of A = [xs; xq]  (20480 x 2048) and of W^T (1024 x 2048)
__device__ __nv_bfloat16 g_A0[(size_t)NZ_ROWS * IN_DIM];
__device__ __nv_bfloat16 g_A1[(size_t)NZ_ROWS * IN_DIM];
__device__ __nv_bfloat16 g_A2[(size_t)NZ_ROWS * IN_DIM];
__device__ __nv_bfloat16 g_WT0[(size_t)Z_DIM * IN_DIM];
__device__ __nv_bfloat16 g_WT1[(size_t)Z_DIM * IN_DIM];
__device__ __nv_bfloat16 g_WT2[(size_t)Z_DIM * IN_DIM];

// ---------------------------------------------------------------------------
// Baseline-PTX helpers (no "a"-arch features: mma.sync / ldmatrix / cp.async)
// ---------------------------------------------------------------------------
__device__ __forceinline__ uint32_t smem_u32(const void* p) {
    uint32_t a;
    asm("{ .reg .u64 t; cvta.to.shared.u64 t, %1; cvt.u32.u64 %0, t; }"
        : "=r"(a) : "l"(p));
    return a;
}

#define CP_ASYNC16(smem_addr, gptr) \
    asm volatile("cp.async.cg.shared.global [%0], [%1], 16;" \
                 :: "r"(smem_addr), "l"(gptr))
#define CP_COMMIT() asm volatile("cp.async.commit_group;" ::: "memory")
#define CP_WAIT1()  asm volatile("cp.async.wait_group 1;" ::: "memory")

#define LDSM_X4(r0, r1, r2, r3, addr) \
    asm volatile("ldmatrix.sync.aligned.m8n8.x4.shared.b16 {%0,%1,%2,%3}, [%4];" \
                 : "=r"(r0), "=r"(r1), "=r"(r2), "=r"(r3) : "r"(addr))

#define MMA_BF16(d0, d1, d2, d3, a0, a1, a2, a3, b0, b1) \
    asm volatile( \
        "mma.sync.aligned.m16n8k16.row.col.f32.bf16.bf16.f32 " \
        "{%0,%1,%2,%3}, {%4,%5,%6,%7}, {%8,%9}, {%0,%1,%2,%3};" \
        : "+f"(d0), "+f"(d1), "+f"(d2), "+f"(d3) \
        : "r"(a0), "r"(a1), "r"(a2), "r"(a3), "r"(b0), "r"(b1))

// Swizzled smem tile layout: logical [128 rows][64 bytes] (32 bf16 per row).
// Rows are paired into 128B physical lines; 16B chunk cc = ((row&1)<<2)|c is
// XOR-swizzled by (row>>1)&7 -> conflict-free LDSM and conflict-free stores.
__device__ __forceinline__ uint32_t tile_off(int row, int c) {
    int cc = ((row & 1) << 2) | c;
    int p  = cc ^ ((row >> 1) & 7);
    return (uint32_t)((row >> 1) * 128 + p * 16);
}

// ---------------------------------------------------------------------------
// bf16 3-way split helpers
// ---------------------------------------------------------------------------
__device__ __forceinline__ void split3(float x, unsigned short& s0,
                                       unsigned short& s1, unsigned short& s2)
{
    __nv_bfloat16 h0 = __float2bfloat16_rn(x);
    float r = x - __bfloat162float(h0);
    __nv_bfloat16 h1 = __float2bfloat16_rn(r);
    float r2 = r - __bfloat162float(h1);
    __nv_bfloat16 h2 = __float2bfloat16_rn(r2);
    s0 = __bfloat16_as_ushort(h0);
    s1 = __bfloat16_as_ushort(h1);
    s2 = __bfloat16_as_ushort(h2);
}

__global__ __launch_bounds__(256) void split_a_kernel(
    const float* __restrict__ src,
    __nv_bfloat16* __restrict__ d0, __nv_bfloat16* __restrict__ d1,
    __nv_bfloat16* __restrict__ d2, int n)
{
    int i = (blockIdx.x * 256 + threadIdx.x) * 4;
    if (i >= n) return;
    float4 v = *(const float4*)(src + i);
    ushort4 o0, o1, o2;
    split3(v.x, o0.x, o1.x, o2.x);
    split3(v.y, o0.y, o1.y, o2.y);
    split3(v.z, o0.z, o1.z, o2.z);
    split3(v.w, o0.w, o1.w, o2.w);
    *(ushort4*)(d0 + i) = o0;
    *(ushort4*)(d1 + i) = o1;
    *(ushort4*)(d2 + i) = o2;
}

// Transpose + split W [2048 x 1024] -> WT splits [1024 x 2048].
__global__ __launch_bounds__(256) void split_wt_kernel(
    const float* __restrict__ W,
    __nv_bfloat16* __restrict__ t0, __nv_bfloat16* __restrict__ t1,
    __nv_bfloat16* __restrict__ t2)
{
    __shared__ float tile[32][33];
    int n0 = blockIdx.x * 32;
    int k0 = blockIdx.y * 32;
    int tx = threadIdx.x & 31;
    int ty0 = threadIdx.x >> 5;
    #pragma unroll
    for (int j = 0; j < 4; j++) {
        int ty = ty0 + j * 8;
        tile[ty][tx] = W[(size_t)(k0 + ty) * Z_DIM + n0 + tx];
    }
    __syncthreads();
    #pragma unroll
    for (int j = 0; j < 4; j++) {
        int ty = ty0 + j * 8;
        float x = tile[tx][ty];
        unsigned short s0, s1, s2;
        split3(x, s0, s1, s2);
        size_t o = (size_t)(n0 + ty) * IN_DIM + k0 + tx;
        t0[o] = __ushort_as_bfloat16(s0);
        t1[o] = __ushort_as_bfloat16(s1);
        t2[o] = __ushort_as_bfloat16(s2);
    }
}

// ---------------------------------------------------------------------------
// GEMM1: bf16x6 split GEMM on mma.sync (HMMA), fp32 accumulate.
// CTA 128x128, BK=32, 2-stage cp.async pipeline, 8 warps (2x4), warp 64x32.
// Passes (ai,bi) with ai+bi<=2: dropped terms <= 2^-27 relative.
// ---------------------------------------------------------------------------
#define GT_TILE  8192                 // one split-tile: 128 rows x 64 B
#define GT_STAGE (6 * GT_TILE)        // 48 KB
#define GT_SMEM  (2 * GT_STAGE)       // 96 KB
#define GT_NCHUNK (IN_DIM / 32)       // 64

__global__ __launch_bounds__(256, 2) void gemm_bf16x6_mma(
    const __nv_bfloat16* __restrict__ A0, const __nv_bfloat16* __restrict__ A1,
    const __nv_bfloat16* __restrict__ A2,
    const __nv_bfloat16* __restrict__ B0, const __nv_bfloat16* __restrict__ B1,
    const __nv_bfloat16* __restrict__ B2,
    float* __restrict__ C)
{
    extern __shared__ char smem[];
    const uint32_t sb = smem_u32(smem);
    const int tid  = threadIdx.x;
    const int wid  = tid >> 5;
    const int lane = tid & 31;
    const int n0 = blockIdx.x * 128;   // z-col tile
    const int m0 = blockIdx.y * 128;   // row tile

    const int wm = wid & 1;            // 0..1 -> 64-row group
    const int wn = wid >> 1;           // 0..3 -> 32-col group
    const int mbase = wm * 64;
    const int nbase = wn * 32;

    const __nv_bfloat16* srcs[6];
    srcs[0] = A0 + (size_t)m0 * IN_DIM;
    srcs[1] = A1 + (size_t)m0 * IN_DIM;
    srcs[2] = A2 + (size_t)m0 * IN_DIM;
    srcs[3] = B0 + (size_t)n0 * IN_DIM;
    srcs[4] = B1 + (size_t)n0 * IN_DIM;
    srcs[5] = B2 + (size_t)n0 * IN_DIM;

    // Per-thread gmem load coords: idx = tid + j*256 -> row = idx>>2, c = idx&3
    const int ldrow0 = tid >> 2;            // j=0 row (0..63)
    const int ldrow1 = (tid + 256) >> 2;    // j=1 row (64..127)
    const int ldc    = tid & 3;
    const uint32_t soff0 = tile_off(ldrow0, ldc);
    const uint32_t soff1 = tile_off(ldrow1, ldc);

    // Precompute LDSM smem offsets (stage-invariant).
    // A frags: (mtile, ksub): row = mbase + mtile*16 + (lane&15), chunk = ksub*2 + (lane>>4)
    uint32_t aoff[4][2];
    #pragma unroll
    for (int mt = 0; mt < 4; mt++)
        #pragma unroll
        for (int ks = 0; ks < 2; ks++)
            aoff[mt][ks] = tile_off(mbase + mt * 16 + (lane & 15),
                                    ks * 2 + (lane >> 4));
    // B frags: pair q covers ntiles 2q,2q+1:
    // row = nbase + (2q + (lane>>4))*8 + (lane&7), chunk = ksub*2 + ((lane>>3)&1)
    uint32_t boff[2][2];
    #pragma unroll
    for (int q = 0; q < 2; q++)
        #pragma unroll
        for (int ks = 0; ks < 2; ks++)
            boff[q][ks] = tile_off(nbase + (2 * q + (lane >> 4)) * 8 + (lane & 7),
                                   ks * 2 + ((lane >> 3) & 1));

    float acc[64];
    #pragma unroll
    for (int i = 0; i < 64; i++) acc[i] = 0.0f;

    // ---- prologue: stage 0 <- chunk 0
    #pragma unroll
    for (int t = 0; t < 6; t++) {
        CP_ASYNC16(sb + t * GT_TILE + soff0,
                   srcs[t] + (size_t)ldrow0 * IN_DIM + ldc * 8);
        CP_ASYNC16(sb + t * GT_TILE + soff1,
                   srcs[t] + (size_t)ldrow1 * IN_DIM + ldc * 8);
    }
    CP_COMMIT();

    const int PAI[6] = {0, 0, 1, 1, 0, 2};
    const int PBI[6] = {0, 1, 0, 1, 2, 0};

    for (int chunk = 0; chunk < GT_NCHUNK; chunk++) {
        // issue next chunk into the other stage
        if (chunk + 1 < GT_NCHUNK) {
            uint32_t st = sb + ((chunk + 1) & 1) * GT_STAGE;
            size_t kn = (size_t)(chunk + 1) * 32;
            #pragma unroll
            for (int t = 0; t < 6; t++) {
                CP_ASYNC16(st + t * GT_TILE + soff0,
                           srcs[t] + (size_t)ldrow0 * IN_DIM + kn + ldc * 8);
                CP_ASYNC16(st + t * GT_TILE + soff1,
                           srcs[t] + (size_t)ldrow1 * IN_DIM + kn + ldc * 8);
            }
        }
        CP_COMMIT();
        CP_WAIT1();
        __syncthreads();

        uint32_t st = sb + (chunk & 1) * GT_STAGE;
        #pragma unroll
        for (int p = 0; p < 6; p++) {
            uint32_t abase = st + PAI[p] * GT_TILE;
            uint32_t bbase = st + (3 + PBI[p]) * GT_TILE;
            #pragma unroll
            for (int ks = 0; ks < 2; ks++) {
                uint32_t af[4][4];
                #pragma unroll
                for (int mt = 0; mt < 4; mt++)
                    LDSM_X4(af[mt][0], af[mt][1], af[mt][2], af[mt][3],
                            abase + aoff[mt][ks]);
                uint32_t bf[2][4];   // [q][2q:kh0, 2q:kh1, 2q+1:kh0, 2q+1:kh1]
                #pragma unroll
                for (int q = 0; q < 2; q++)
                    LDSM_X4(bf[q][0], bf[q][1], bf[q][2], bf[q][3],
                            bbase + boff[q][ks]);
                #pragma unroll
                for (int mt = 0; mt < 4; mt++) {
                    #pragma unroll
                    for (int nt = 0; nt < 4; nt++) {
                        float* d = &acc[(mt * 4 + nt) * 4];
                        int q = nt >> 1, h = (nt & 1) * 2;
                        MMA_BF16(d[0], d[1], d[2], d[3],
                                 af[mt][0], af[mt][1], af[mt][2], af[mt][3],
                                 bf[q][h], bf[q][h + 1]);
                    }
                }
            }
        }
        __syncthreads();
    }

    // Epilogue: direct float2 stores.
    #pragma unroll
    for (int mt = 0; mt < 4; mt++) {
        #pragma unroll
        for (int nt = 0; nt < 4; nt++) {
            const float* d = &acc[(mt * 4 + nt) * 4];
            int r0 = m0 + mbase + mt * 16 + (lane >> 2);
            int cc = n0 + nbase + nt * 8 + (lane & 3) * 2;
            *(float2*)(C + (size_t)r0 * Z_DIM + cc) = make_float2(d[0], d[1]);
            *(float2*)(C + (size_t)(r0 + 8) * Z_DIM + cc) = make_float2(d[2], d[3]);
        }
    }
}

// ---------------------------------------------------------------------------
// Query row norms in fp64, rounded once to fp32.
// ---------------------------------------------------------------------------
__global__ __launch_bounds__(256) void qnorm_kernel(
    const float* __restrict__ zq, float* __restrict__ qn)
{
    int q = blockIdx.x;
    const float* row = zq + (size_t)q * Z_DIM;
    int tid = threadIdx.x;
    double s = 0.0;
    for (int d = tid; d < Z_DIM; d += 256) {
        double v = (double)row[d];
        s = fma(v, v, s);
    }
    __shared__ double red[256];
    red[tid] = s;
    __syncthreads();
    for (int o = 128; o > 0; o >>= 1) {
        if (tid < o) red[tid] += red[tid + o];
        __syncthreads();
    }
    if (tid == 0) qn[q] = (float)red[0];
}

// ---------------------------------------------------------------------------
// Per-class assignment (fp64) + centroids (fp64 sums -> fp32) + proto norms.
// ---------------------------------------------------------------------------
__global__ __launch_bounds__(256) void centroid_kernel(
    const float* __restrict__ z,
    float* __restrict__ protosT,
    float* __restrict__ proto_sq)
{
    int c = blockIdx.x;
    const float* zs = z + (size_t)c * N_SUPPORT * Z_DIM;
    int tid = threadIdx.x;
    int wid = tid >> 5, lane = tid & 31;

    __shared__ double d0s[N_SUPPORT], d1s[N_SUPPORT];
    __shared__ int    sAssign[N_SUPPORT];
    __shared__ int    sCnt0, sCnt1;

    for (int s = wid; s < N_SUPPORT; s += 8) {
        double d0 = 0.0, d1 = 0.0;
        for (int d = lane; d < Z_DIM; d += 32) {
            double v = (double)zs[(size_t)s * Z_DIM + d];
            double a = v - (double)zs[d];
            double b = v - (double)zs[(size_t)Z_DIM + d];
            d0 = fma(a, a, d0);
            d1 = fma(b, b, d1);
        }
        #pragma unroll
        for (int o = 16; o > 0; o >>= 1) {
            d0 += __shfl_down_sync(0xffffffffu, d0, o);
            d1 += __shfl_down_sync(0xffffffffu, d1, o);
        }
        if (lane == 0) { d0s[s] = d0; d1s[s] = d1; }
    }
    __syncthreads();

    if (tid < N_SUPPORT)
        sAssign[tid] = (d1s[tid] < d0s[tid]) ? 1 : 0;
    __syncthreads();

    if (tid == 0) {
        int c1 = 0;
        for (int s = 0; s < N_SUPPORT; s++) c1 += sAssign[s];
        sCnt1 = c1;
        sCnt0 = N_SUPPORT - c1;
    }
    __syncthreads();

    int cnt0 = sCnt0, cnt1 = sCnt1;

    double sq0 = 0.0, sq1 = 0.0;
    for (int d = tid; d < Z_DIM; d += 256) {
        double s0 = 0.0, s1 = 0.0;
        for (int s = 0; s < N_SUPPORT; s++) {
            double v = (double)zs[(size_t)s * Z_DIM + d];
            if (sAssign[s]) s1 += v; else s0 += v;
        }
        float c0f, c1f;
        c0f = (cnt0 > 0) ? (float)(s0 / (double)(cnt0 > 1 ? cnt0 : 1)) : zs[d];
        c1f = (cnt1 > 0) ? (float)(s1 / (double)(cnt1 > 1 ? cnt1 : 1))
                         : zs[(size_t)Z_DIM + d];
        protosT[(size_t)d * N_PROTO + 2 * c]     = c0f;
        protosT[(size_t)d * N_PROTO + 2 * c + 1] = c1f;
        sq0 = fma((double)c0f, (double)c0f, sq0);
        sq1 = fma((double)c1f, (double)c1f, sq1);
    }

    __shared__ double r0[256], r1[256];
    r0[tid] = sq0; r1[tid] = sq1;
    __syncthreads();
    for (int o = 128; o > 0; o >>= 1) {
        if (tid < o) { r0[tid] += r0[tid + o]; r1[tid] += r1[tid + o]; }
        __syncthreads();
    }
    if (tid == 0) {
        proto_sq[2 * c]     = (float)r0[0];
        proto_sq[2 * c + 1] = (float)r1[0];
    }
}

// ---------------------------------------------------------------------------
// GEMM2 + epilogue (fp32 SIMT): d = (qn + pn) - 2*S; clamp; min over K=2.
// ---------------------------------------------------------------------------
#define BM 128
#define BN 128
#define BK 16
#define TM 8
#define TN 8

__global__ __launch_bounds__(256) void dist_gemm_kernel(
    const float* __restrict__ A, const float* __restrict__ B,
    const float* __restrict__ qn, const float* __restrict__ pn,
    float* __restrict__ dists)
{
    const int Nn = N_PROTO;
    const int Kk = Z_DIM;

    __shared__ float As[BK][BM];
    __shared__ float Bs[BK][BN];

    const int bx = blockIdx.x;
    const int by = blockIdx.y;
    const int tid = threadIdx.x;
    const int tx = tid & 15;
    const int ty = tid >> 4;

    const float* Ablk = A + (size_t)by * BM * Kk;
    const float* Bblk = B + (size_t)bx * BN;

    float acc[TM][TN];
    #pragma unroll
    for (int m = 0; m < TM; m++)
        #pragma unroll
        for (int n = 0; n < TN; n++) acc[m][n] = 0.0f;

    for (int k0 = 0; k0 < Kk; k0 += BK) {
        #pragma unroll
        for (int i = 0; i < 2; i++) {
            int idx = tid + i * 256;
            int row = idx >> 2;
            int c4  = idx & 3;
            float4 v = *(const float4*)(Ablk + (size_t)row * Kk + k0 + c4 * 4);
            As[c4 * 4 + 0][row] = v.x;
            As[c4 * 4 + 1][row] = v.y;
            As[c4 * 4 + 2][row] = v.z;
            As[c4 * 4 + 3][row] = v.w;
        }
        #pragma unroll
        for (int i = 0; i < 2; i++) {
            int idx = tid + i * 256;
            int row = idx >> 5;
            int c4  = idx & 31;
            float4 v = *(const float4*)(Bblk + (size_t)(k0 + row) * Nn + c4 * 4);
            *(float4*)&Bs[row][c4 * 4] = v;
        }
        __syncthreads();

        float part[TM][TN];
        #pragma unroll
        for (int m = 0; m < TM; m++)
            #pragma unroll
            for (int n = 0; n < TN; n++) part[m][n] = 0.0f;

        #pragma unroll
        for (int k = 0; k < BK; k++) {
            float a[TM], b[TN];
            #pragma unroll
            for (int m = 0; m < TM; m++) a[m] = As[k][ty * TM + m];
            #pragma unroll
            for (int n = 0; n < TN; n++) b[n] = Bs[k][tx * TN + n];
            #pragma unroll
            for (int m = 0; m < TM; m++)
                #pragma unroll
                for (int n = 0; n < TN; n++)
                    part[m][n] = fmaf(a[m], b[n], part[m][n]);
        }
        #pragma unroll
        for (int m = 0; m < TM; m++)
            #pragma unroll
            for (int n = 0; n < TN; n++) acc[m][n] += part[m][n];
        __syncthreads();
    }

    #pragma unroll
    for (int m = 0; m < TM; m++) {
        int q = by * BM + ty * TM + m;
        float qv = qn[q];
        #pragma unroll
        for (int n = 0; n < TN; n += 2) {
            int gcol = bx * BN + tx * TN + n;
            float t0 = __fadd_rn(qv, pn[gcol]);
            float t1 = __fadd_rn(qv, pn[gcol + 1]);
            float d0 = __fadd_rn(t0, -__fmul_rn(2.0f, acc[m][n]));
            float d1 = __fadd_rn(t1, -__fmul_rn(2.0f, acc[m][n + 1]));
            d0 = fmaxf(d0, 0.0f);
            d1 = fmaxf(d1, 0.0f);
            dists[(size_t)q * N_CLASS + (gcol >> 1)] = fminf(d0, d1);
        }
    }
}

// ---------------------------------------------------------------------------
// Per-query loss + accuracy (epsilon-snapped argmax, first index on tie).
// ---------------------------------------------------------------------------
__global__ __launch_bounds__(128) void loss_kernel(
    const float* __restrict__ dists,
    float* __restrict__ lpart, float* __restrict__ apart)
{
    int q = blockIdx.x;
    int c = threadIdx.x;
    float v = dists[(size_t)q * N_CLASS + c];

    __shared__ float sv[128];
    __shared__ float mv[128];
    sv[c] = v; mv[c] = v;
    __syncthreads();

    for (int o = 64; o > 0; o >>= 1) {
        if (c < o) {
            sv[c] += sv[c + o];
            mv[c] = fmaxf(mv[c], mv[c + o]);
        }
        __syncthreads();
    }
    float m = mv[0];
    __syncthreads();

    __shared__ int ci[128];
    float thresh = fmaf(m, -3e-7f, m);
    ci[c] = (v >= thresh) ? c : (N_CLASS + 1);
    __syncthreads();
    for (int o = 64; o > 0; o >>= 1) {
        if (c < o) ci[c] = min(ci[c], ci[c + o]);
        __syncthreads();
    }

    if (c == 0) {
        int ct = q >> 7;
        float vt = dists[(size_t)q * N_CLASS + ct];
        lpart[q] = logf(sv[0]) - logf(vt);
        apart[q] = (ci[0] == ct) ? 1.0f : 0.0f;
    }
}

// ---------------------------------------------------------------------------
// Deterministic final reduction (fp64).
// ---------------------------------------------------------------------------
__global__ __launch_bounds__(256) void final_kernel(
    const float* __restrict__ lpart, const float* __restrict__ apart,
    float* __restrict__ out)
{
    __shared__ double ls[256], as_[256];
    int tid = threadIdx.x;
    double l = 0.0, a = 0.0;
    int base = tid * (NQ_ROWS / 256);
    for (int i = 0; i < NQ_ROWS / 256; i++) {
        l += (double)lpart[base + i];
        a += (double)apart[base + i];
    }
    ls[tid] = l; as_[tid] = a;
    __syncthreads();
    for (int o = 128; o > 0; o >>= 1) {
        if (tid < o) { ls[tid] += ls[tid + o]; as_[tid] += as_[tid + o]; }
        __syncthreads();
    }
    if (tid == 0) {
        out[0] = (float)(ls[0] / (double)NQ_ROWS);
        out[1] = (float)(as_[0] / (double)NQ_ROWS);
    }
}

// ---------------------------------------------------------------------------
// Launch
// ---------------------------------------------------------------------------
extern "C" void kernel_launch(void* const* d_in, const int* in_sizes, int n_in,
                              void* d_out, int out_size)
{
    const float* xs = (const float*)d_in[0];
    const float* xq = (const float*)d_in[1];
    const float* W  = (const float*)d_in[2];
    float* out = (float*)d_out;

    float* z;        cudaGetSymbolAddress((void**)&z, g_z);
    float* protosT;  cudaGetSymbolAddress((void**)&protosT, g_protosT);
    float* proto_sq; cudaGetSymbolAddress((void**)&proto_sq, g_proto_sq);
    float* qnorm;    cudaGetSymbolAddress((void**)&qnorm, g_qnorm);
    float* dists;    cudaGetSymbolAddress((void**)&dists, g_dists);
    float* lpart;    cudaGetSymbolAddress((void**)&lpart, g_lpart);
    float* apart;    cudaGetSymbolAddress((void**)&apart, g_apart);
    __nv_bfloat16 *A0, *A1, *A2, *WT0, *WT1, *WT2;
    cudaGetSymbolAddress((void**)&A0, g_A0);
    cudaGetSymbolAddress((void**)&A1, g_A1);
    cudaGetSymbolAddress((void**)&A2, g_A2);
    cudaGetSymbolAddress((void**)&WT0, g_WT0);
    cudaGetSymbolAddress((void**)&WT1, g_WT1);
    cudaGetSymbolAddress((void**)&WT2, g_WT2);

    float* zq = z + (size_t)NS_ROWS * Z_DIM;

    cudaFuncSetAttribute(gemm_bf16x6_mma,
                         cudaFuncAttributeMaxDynamicSharedMemorySize, GT_SMEM);

    // 1) Split inputs into bf16 triples
    int nxs = NS_ROWS * IN_DIM;
    int nxq = NQ_ROWS * IN_DIM;
    size_t offq = (size_t)NS_ROWS * IN_DIM;
    split_a_kernel<<<nxs / 4 / 256, 256>>>(xs, A0, A1, A2, nxs);
    split_a_kernel<<<nxq / 4 / 256, 256>>>(xq, A0 + offq, A1 + offq, A2 + offq, nxq);
    split_wt_kernel<<<dim3(Z_DIM / 32, IN_DIM / 32), 256>>>(W, WT0, WT1, WT2);

    // 2) Projection GEMM on HMMA (bf16x6, fp32 accumulate)
    gemm_bf16x6_mma<<<dim3(Z_DIM / 128, NZ_ROWS / 128), 256, GT_SMEM>>>(
        A0, A1, A2, WT0, WT1, WT2, z);

    // 3) Norms, centroids
    qnorm_kernel<<<NQ_ROWS, 256>>>(zq, qnorm);
    centroid_kernel<<<N_CLASS, 256>>>(z, protosT, proto_sq);

    // 4) Query-proto distances
    dim3 gd(N_PROTO / BN, NQ_ROWS / BM);
    dist_gemm_kernel<<<gd, 256>>>(zq, protosT, qnorm, proto_sq, dists);

    // 5) Loss / acc
    loss_kernel<<<NQ_ROWS, 128>>>(dists, lpart, apart);
    final_kernel<<<1, 256>>>(lpart, apart, out);
}

// round 7
// speedup vs baseline: 1.9148x; 1.2567x over previous
#include <cuda_runtime.h>
#include <cuda_bf16.h>
#include <math.h>
#include <stdint.h>

// ---------------------------------------------------------------------------
// Problem constants
// ---------------------------------------------------------------------------
#define N_CLASS   128
#define N_SUPPORT 32
#define N_QUERY   128
#define IN_DIM    2048
#define Z_DIM     1024
#define KCLUST    2

#define NS_ROWS (N_CLASS * N_SUPPORT)   // 4096
#define NQ_ROWS (N_CLASS * N_QUERY)    // 16384
#define NZ_ROWS (NS_ROWS + NQ_ROWS)    // 20480
#define N_PROTO (N_CLASS * KCLUST)     // 256

// ---------------------------------------------------------------------------
// Scratch (device globals; no allocation allowed)
// ---------------------------------------------------------------------------
__device__ float g_z[(size_t)NZ_ROWS * Z_DIM];          // 80 MB
__device__ float g_protos[(size_t)N_PROTO * Z_DIM];     // 1 MB row-major
__device__ float g_proto_sq[N_PROTO];
__device__ float g_qnorm[NQ_ROWS];
__device__ float g_dists[(size_t)NQ_ROWS * N_CLASS];    // 8 MB
__device__ float g_lpart[NQ_ROWS];
__device__ float g_apart[NQ_ROWS];

// bf16 splits
__device__ __nv_bfloat16 g_A0[(size_t)NZ_ROWS * IN_DIM];
__device__ __nv_bfloat16 g_A1[(size_t)NZ_ROWS * IN_DIM];
__device__ __nv_bfloat16 g_A2[(size_t)NZ_ROWS * IN_DIM];
__device__ __nv_bfloat16 g_WT0[(size_t)Z_DIM * IN_DIM];
__device__ __nv_bfloat16 g_WT1[(size_t)Z_DIM * IN_DIM];
__device__ __nv_bfloat16 g_WT2[(size_t)Z_DIM * IN_DIM];
__device__ __nv_bfloat16 g_Zq0[(size_t)NQ_ROWS * Z_DIM];
__device__ __nv_bfloat16 g_Zq1[(size_t)NQ_ROWS * Z_DIM];
__device__ __nv_bfloat16 g_Zq2[(size_t)NQ_ROWS * Z_DIM];
__device__ __nv_bfloat16 g_P0[(size_t)N_PROTO * Z_DIM];
__device__ __nv_bfloat16 g_P1[(size_t)N_PROTO * Z_DIM];
__device__ __nv_bfloat16 g_P2[(size_t)N_PROTO * Z_DIM];

// ---------------------------------------------------------------------------
// Baseline-PTX helpers (mma.sync / ldmatrix / cp.async)
// ---------------------------------------------------------------------------
__device__ __forceinline__ uint32_t smem_u32(const void* p) {
    uint32_t a;
    asm("{ .reg .u64 t; cvta.to.shared.u64 t, %1; cvt.u32.u64 %0, t; }"
        : "=r"(a) : "l"(p));
    return a;
}

#define CP_ASYNC16(smem_addr, gptr) \
    asm volatile("cp.async.cg.shared.global [%0], [%1], 16;" \
                 :: "r"(smem_addr), "l"(gptr))
#define CP_COMMIT() asm volatile("cp.async.commit_group;" ::: "memory")
#define CP_WAIT1()  asm volatile("cp.async.wait_group 1;" ::: "memory")

#define LDSM_X4(r0, r1, r2, r3, addr) \
    asm volatile("ldmatrix.sync.aligned.m8n8.x4.shared.b16 {%0,%1,%2,%3}, [%4];" \
                 : "=r"(r0), "=r"(r1), "=r"(r2), "=r"(r3) : "r"(addr))

#define MMA_BF16(d0, d1, d2, d3, a0, a1, a2, a3, b0, b1) \
    asm volatile( \
        "mma.sync.aligned.m16n8k16.row.col.f32.bf16.bf16.f32 " \
        "{%0,%1,%2,%3}, {%4,%5,%6,%7}, {%8,%9}, {%0,%1,%2,%3};" \
        : "+f"(d0), "+f"(d1), "+f"(d2), "+f"(d3) \
        : "r"(a0), "r"(a1), "r"(a2), "r"(a3), "r"(b0), "r"(b1))

// Swizzled smem tile: logical [128 rows][64 B]; rows paired into 128B lines,
// 16B chunk cc = ((row&1)<<2)|c XOR-swizzled by (row>>1)&7.
__device__ __forceinline__ uint32_t tile_off(int row, int c) {
    int cc = ((row & 1) << 2) | c;
    int p  = cc ^ ((row >> 1) & 7);
    return (uint32_t)((row >> 1) * 128 + p * 16);
}

// ---------------------------------------------------------------------------
// bf16 3-way split helpers
// ---------------------------------------------------------------------------
__device__ __forceinline__ void split3(float x, unsigned short& s0,
                                       unsigned short& s1, unsigned short& s2)
{
    __nv_bfloat16 h0 = __float2bfloat16_rn(x);
    float r = x - __bfloat162float(h0);
    __nv_bfloat16 h1 = __float2bfloat16_rn(r);
    float r2 = r - __bfloat162float(h1);
    __nv_bfloat16 h2 = __float2bfloat16_rn(r2);
    s0 = __bfloat16_as_ushort(h0);
    s1 = __bfloat16_as_ushort(h1);
    s2 = __bfloat16_as_ushort(h2);
}

__global__ __launch_bounds__(256) void split_a_kernel(
    const float* __restrict__ src,
    __nv_bfloat16* __restrict__ d0, __nv_bfloat16* __restrict__ d1,
    __nv_bfloat16* __restrict__ d2, int n)
{
    int i = (blockIdx.x * 256 + threadIdx.x) * 4;
    if (i >= n) return;
    float4 v = *(const float4*)(src + i);
    ushort4 o0, o1, o2;
    split3(v.x, o0.x, o1.x, o2.x);
    split3(v.y, o0.y, o1.y, o2.y);
    split3(v.z, o0.z, o1.z, o2.z);
    split3(v.w, o0.w, o1.w, o2.w);
    *(ushort4*)(d0 + i) = o0;
    *(ushort4*)(d1 + i) = o1;
    *(ushort4*)(d2 + i) = o2;
}

// Transpose + split W [2048 x 1024] -> WT splits [1024 x 2048].
__global__ __launch_bounds__(256) void split_wt_kernel(
    const float* __restrict__ W,
    __nv_bfloat16* __restrict__ t0, __nv_bfloat16* __restrict__ t1,
    __nv_bfloat16* __restrict__ t2)
{
    __shared__ float tile[32][33];
    int n0 = blockIdx.x * 32;
    int k0 = blockIdx.y * 32;
    int tx = threadIdx.x & 31;
    int ty0 = threadIdx.x >> 5;
    #pragma unroll
    for (int j = 0; j < 4; j++) {
        int ty = ty0 + j * 8;
        tile[ty][tx] = W[(size_t)(k0 + ty) * Z_DIM + n0 + tx];
    }
    __syncthreads();
    #pragma unroll
    for (int j = 0; j < 4; j++) {
        int ty = ty0 + j * 8;
        float x = tile[tx][ty];
        unsigned short s0, s1, s2;
        split3(x, s0, s1, s2);
        size_t o = (size_t)(n0 + ty) * IN_DIM + k0 + tx;
        t0[o] = __ushort_as_bfloat16(s0);
        t1[o] = __ushort_as_bfloat16(s1);
        t2[o] = __ushort_as_bfloat16(s2);
    }
}

// Split one zq row into bf16 triple AND compute its fp64 norm -> fp32.
__global__ __launch_bounds__(256) void split_zq_norm_kernel(
    const float* __restrict__ zq,
    __nv_bfloat16* __restrict__ d0, __nv_bfloat16* __restrict__ d1,
    __nv_bfloat16* __restrict__ d2, float* __restrict__ qn)
{
    int q = blockIdx.x;
    int tid = threadIdx.x;
    size_t o = (size_t)q * Z_DIM + tid * 4;
    float4 v = *(const float4*)(zq + o);
    ushort4 o0, o1, o2;
    split3(v.x, o0.x, o1.x, o2.x);
    split3(v.y, o0.y, o1.y, o2.y);
    split3(v.z, o0.z, o1.z, o2.z);
    split3(v.w, o0.w, o1.w, o2.w);
    *(ushort4*)(d0 + o) = o0;
    *(ushort4*)(d1 + o) = o1;
    *(ushort4*)(d2 + o) = o2;

    double s = 0.0;
    s = fma((double)v.x, (double)v.x, s);
    s = fma((double)v.y, (double)v.y, s);
    s = fma((double)v.z, (double)v.z, s);
    s = fma((double)v.w, (double)v.w, s);
    __shared__ double red[256];
    red[tid] = s;
    __syncthreads();
    for (int o2_ = 128; o2_ > 0; o2_ >>= 1) {
        if (tid < o2_) red[tid] += red[tid + o2_];
        __syncthreads();
    }
    if (tid == 0) qn[q] = (float)red[0];
}

// ---------------------------------------------------------------------------
// Unified bf16x6 split GEMM on HMMA, fp32 accumulate.
// CTA 128x128, BK=32, 2-stage cp.async pipeline, 8 warps (2x4), warp 64x32.
// Fragment-reuse mainloop: B frags for all 3 splits resident, A streamed.
// EPI=0: plain C store (width Z_DIM). EPI=1: protonet dist epilogue.
// ---------------------------------------------------------------------------
#define GT_TILE  8192                 // one split-tile: 128 rows x 64 B
#define GT_STAGE (6 * GT_TILE)        // 48 KB
#define GT_SMEM  (2 * GT_STAGE)       // 96 KB

template<int K_TOTAL, int EPI>
__global__ __launch_bounds__(256, 2) void gemm6_kernel(
    const __nv_bfloat16* __restrict__ A0, const __nv_bfloat16* __restrict__ A1,
    const __nv_bfloat16* __restrict__ A2,
    const __nv_bfloat16* __restrict__ B0, const __nv_bfloat16* __restrict__ B1,
    const __nv_bfloat16* __restrict__ B2,
    float* __restrict__ out,
    const float* __restrict__ qn, const float* __restrict__ pn)
{
    extern __shared__ char smem[];
    const uint32_t sb = smem_u32(smem);
    const int tid  = threadIdx.x;
    const int wid  = tid >> 5;
    const int lane = tid & 31;
    const int n0 = blockIdx.x * 128;
    const int m0 = blockIdx.y * 128;

    const int wm = wid & 1;
    const int wn = wid >> 1;
    const int mbase = wm * 64;
    const int nbase = wn * 32;

    const __nv_bfloat16* srcs[6];
    srcs[0] = A0 + (size_t)m0 * K_TOTAL;
    srcs[1] = A1 + (size_t)m0 * K_TOTAL;
    srcs[2] = A2 + (size_t)m0 * K_TOTAL;
    srcs[3] = B0 + (size_t)n0 * K_TOTAL;
    srcs[4] = B1 + (size_t)n0 * K_TOTAL;
    srcs[5] = B2 + (size_t)n0 * K_TOTAL;

    const int ldrow0 = tid >> 2;
    const int ldrow1 = (tid + 256) >> 2;
    const int ldc    = tid & 3;
    const uint32_t soff0 = tile_off(ldrow0, ldc);
    const uint32_t soff1 = tile_off(ldrow1, ldc);

    float acc[64];
    #pragma unroll
    for (int i = 0; i < 64; i++) acc[i] = 0.0f;

    // prologue: stage 0 <- chunk 0
    #pragma unroll
    for (int t = 0; t < 6; t++) {
        CP_ASYNC16(sb + t * GT_TILE + soff0,
                   srcs[t] + (size_t)ldrow0 * K_TOTAL + ldc * 8);
        CP_ASYNC16(sb + t * GT_TILE + soff1,
                   srcs[t] + (size_t)ldrow1 * K_TOTAL + ldc * 8);
    }
    CP_COMMIT();

    const int NCHUNK = K_TOTAL / 32;
    for (int chunk = 0; chunk < NCHUNK; chunk++) {
        if (chunk + 1 < NCHUNK) {
            uint32_t st = sb + ((chunk + 1) & 1) * GT_STAGE;
            size_t kn = (size_t)(chunk + 1) * 32;
            #pragma unroll
            for (int t = 0; t < 6; t++) {
                CP_ASYNC16(st + t * GT_TILE + soff0,
                           srcs[t] + (size_t)ldrow0 * K_TOTAL + kn + ldc * 8);
                CP_ASYNC16(st + t * GT_TILE + soff1,
                           srcs[t] + (size_t)ldrow1 * K_TOTAL + kn + ldc * 8);
            }
        }
        CP_COMMIT();
        CP_WAIT1();
        __syncthreads();

        uint32_t st = sb + (chunk & 1) * GT_STAGE;
        #pragma unroll
        for (int ks = 0; ks < 2; ks++) {
            // B fragments for all 3 splits: resident (24 regs)
            uint32_t bfr[3][2][4];
            #pragma unroll
            for (int bj = 0; bj < 3; bj++) {
                #pragma unroll
                for (int q = 0; q < 2; q++) {
                    uint32_t off = tile_off(
                        nbase + (2 * q + (lane >> 4)) * 8 + (lane & 7),
                        ks * 2 + ((lane >> 3) & 1));
                    LDSM_X4(bfr[bj][q][0], bfr[bj][q][1],
                            bfr[bj][q][2], bfr[bj][q][3],
                            st + (3 + bj) * GT_TILE + off);
                }
            }
            // stream A per split index; fire all (ai,bj) with ai+bj<=2
            #pragma unroll
            for (int ai = 0; ai < 3; ai++) {
                uint32_t af[4][4];
                #pragma unroll
                for (int mt = 0; mt < 4; mt++) {
                    uint32_t off = tile_off(mbase + mt * 16 + (lane & 15),
                                            ks * 2 + (lane >> 4));
                    LDSM_X4(af[mt][0], af[mt][1], af[mt][2], af[mt][3],
                            st + ai * GT_TILE + off);
                }
                #pragma unroll
                for (int bj = 0; bj < 3; bj++) {
                    if (ai + bj > 2) continue;
                    #pragma unroll
                    for (int mt = 0; mt < 4; mt++) {
                        #pragma unroll
                        for (int nt = 0; nt < 4; nt++) {
                            float* d = &acc[(mt * 4 + nt) * 4];
                            int q = nt >> 1, h = (nt & 1) * 2;
                            MMA_BF16(d[0], d[1], d[2], d[3],
                                     af[mt][0], af[mt][1], af[mt][2], af[mt][3],
                                     bfr[bj][q][h], bfr[bj][q][h + 1]);
                        }
                    }
                }
            }
        }
        __syncthreads();
    }

    if (EPI == 0) {
        // plain store, row width Z_DIM
        #pragma unroll
        for (int mt = 0; mt < 4; mt++) {
            #pragma unroll
            for (int nt = 0; nt < 4; nt++) {
                const float* d = &acc[(mt * 4 + nt) * 4];
                int r0 = m0 + mbase + mt * 16 + (lane >> 2);
                int cc = n0 + nbase + nt * 8 + (lane & 3) * 2;
                *(float2*)(out + (size_t)r0 * Z_DIM + cc) =
                    make_float2(d[0], d[1]);
                *(float2*)(out + (size_t)(r0 + 8) * Z_DIM + cc) =
                    make_float2(d[2], d[3]);
            }
        }
    } else {
        // protonet distance epilogue: d = (qn+pn) - 2S, clamp, min over pair
        #pragma unroll
        for (int mt = 0; mt < 4; mt++) {
            int r0 = m0 + mbase + mt * 16 + (lane >> 2);
            float qv0 = qn[r0];
            float qv1 = qn[r0 + 8];
            #pragma unroll
            for (int nt = 0; nt < 4; nt++) {
                const float* d = &acc[(mt * 4 + nt) * 4];
                int cc = n0 + nbase + nt * 8 + (lane & 3) * 2;  // even proto
                float p0 = pn[cc], p1 = pn[cc + 1];
                int cls = cc >> 1;
                float e0 = __fadd_rn(__fadd_rn(qv0, p0),
                                     -__fmul_rn(2.0f, d[0]));
                float e1 = __fadd_rn(__fadd_rn(qv0, p1),
                                     -__fmul_rn(2.0f, d[1]));
                out[(size_t)r0 * N_CLASS + cls] =
                    fminf(fmaxf(e0, 0.0f), fmaxf(e1, 0.0f));
                float e2 = __fadd_rn(__fadd_rn(qv1, p0),
                                     -__fmul_rn(2.0f, d[2]));
                float e3 = __fadd_rn(__fadd_rn(qv1, p1),
                                     -__fmul_rn(2.0f, d[3]));
                out[(size_t)(r0 + 8) * N_CLASS + cls] =
                    fminf(fmaxf(e2, 0.0f), fmaxf(e3, 0.0f));
            }
        }
    }
}

// ---------------------------------------------------------------------------
// Per-class assignment (fp64) + centroids (fp64 sums -> fp32) + proto norms.
// Protos written row-major [N_PROTO][Z_DIM].
// ---------------------------------------------------------------------------
__global__ __launch_bounds__(256) void centroid_kernel(
    const float* __restrict__ z,
    float* __restrict__ protos,
    float* __restrict__ proto_sq)
{
    int c = blockIdx.x;
    const float* zs = z + (size_t)c * N_SUPPORT * Z_DIM;
    int tid = threadIdx.x;
    int wid = tid >> 5, lane = tid & 31;

    __shared__ double d0s[N_SUPPORT], d1s[N_SUPPORT];
    __shared__ int    sAssign[N_SUPPORT];
    __shared__ int    sCnt0, sCnt1;

    for (int s = wid; s < N_SUPPORT; s += 8) {
        double d0 = 0.0, d1 = 0.0;
        for (int d = lane; d < Z_DIM; d += 32) {
            double v = (double)zs[(size_t)s * Z_DIM + d];
            double a = v - (double)zs[d];
            double b = v - (double)zs[(size_t)Z_DIM + d];
            d0 = fma(a, a, d0);
            d1 = fma(b, b, d1);
        }
        #pragma unroll
        for (int o = 16; o > 0; o >>= 1) {
            d0 += __shfl_down_sync(0xffffffffu, d0, o);
            d1 += __shfl_down_sync(0xffffffffu, d1, o);
        }
        if (lane == 0) { d0s[s] = d0; d1s[s] = d1; }
    }
    __syncthreads();

    if (tid < N_SUPPORT)
        sAssign[tid] = (d1s[tid] < d0s[tid]) ? 1 : 0;
    __syncthreads();

    if (tid == 0) {
        int c1 = 0;
        for (int s = 0; s < N_SUPPORT; s++) c1 += sAssign[s];
        sCnt1 = c1;
        sCnt0 = N_SUPPORT - c1;
    }
    __syncthreads();

    int cnt0 = sCnt0, cnt1 = sCnt1;

    double sq0 = 0.0, sq1 = 0.0;
    for (int d = tid; d < Z_DIM; d += 256) {
        double s0 = 0.0, s1 = 0.0;
        for (int s = 0; s < N_SUPPORT; s++) {
            double v = (double)zs[(size_t)s * Z_DIM + d];
            if (sAssign[s]) s1 += v; else s0 += v;
        }
        float c0f, c1f;
        c0f = (cnt0 > 0) ? (float)(s0 / (double)(cnt0 > 1 ? cnt0 : 1)) : zs[d];
        c1f = (cnt1 > 0) ? (float)(s1 / (double)(cnt1 > 1 ? cnt1 : 1))
                         : zs[(size_t)Z_DIM + d];
        protos[(size_t)(2 * c) * Z_DIM + d]     = c0f;
        protos[(size_t)(2 * c + 1) * Z_DIM + d] = c1f;
        sq0 = fma((double)c0f, (double)c0f, sq0);
        sq1 = fma((double)c1f, (double)c1f, sq1);
    }

    __shared__ double r0[256], r1[256];
    r0[tid] = sq0; r1[tid] = sq1;
    __syncthreads();
    for (int o = 128; o > 0; o >>= 1) {
        if (tid < o) { r0[tid] += r0[tid + o]; r1[tid] += r1[tid + o]; }
        __syncthreads();
    }
    if (tid == 0) {
        proto_sq[2 * c]     = (float)r0[0];
        proto_sq[2 * c + 1] = (float)r1[0];
    }
}

// ---------------------------------------------------------------------------
// Per-query loss + accuracy (epsilon-snapped argmax, first index on tie).
// ---------------------------------------------------------------------------
__global__ __launch_bounds__(128) void loss_kernel(
    const float* __restrict__ dists,
    float* __restrict__ lpart, float* __restrict__ apart)
{
    int q = blockIdx.x;
    int c = threadIdx.x;
    float v = dists[(size_t)q * N_CLASS + c];

    __shared__ float sv[128];
    __shared__ float mv[128];
    sv[c] = v; mv[c] = v;
    __syncthreads();

    for (int o = 64; o > 0; o >>= 1) {
        if (c < o) {
            sv[c] += sv[c + o];
            mv[c] = fmaxf(mv[c], mv[c + o]);
        }
        __syncthreads();
    }
    float m = mv[0];
    __syncthreads();

    __shared__ int ci[128];
    float thresh = fmaf(m, -3e-7f, m);
    ci[c] = (v >= thresh) ? c : (N_CLASS + 1);
    __syncthreads();
    for (int o = 64; o > 0; o >>= 1) {
        if (c < o) ci[c] = min(ci[c], ci[c + o]);
        __syncthreads();
    }

    if (c == 0) {
        int ct = q >> 7;
        float vt = dists[(size_t)q * N_CLASS + ct];
        lpart[q] = logf(sv[0]) - logf(vt);
        apart[q] = (ci[0] == ct) ? 1.0f : 0.0f;
    }
}

// ---------------------------------------------------------------------------
// Deterministic final reduction (fp64).
// ---------------------------------------------------------------------------
__global__ __launch_bounds__(256) void final_kernel(
    const float* __restrict__ lpart, const float* __restrict__ apart,
    float* __restrict__ out)
{
    __shared__ double ls[256], as_[256];
    int tid = threadIdx.x;
    double l = 0.0, a = 0.0;
    int base = tid * (NQ_ROWS / 256);
    for (int i = 0; i < NQ_ROWS / 256; i++) {
        l += (double)lpart[base + i];
        a += (double)apart[base + i];
    }
    ls[tid] = l; as_[tid] = a;
    __syncthreads();
    for (int o = 128; o > 0; o >>= 1) {
        if (tid < o) { ls[tid] += ls[tid + o]; as_[tid] += as_[tid + o]; }
        __syncthreads();
    }
    if (tid == 0) {
        out[0] = (float)(ls[0] / (double)NQ_ROWS);
        out[1] = (float)(as_[0] / (double)NQ_ROWS);
    }
}

// ---------------------------------------------------------------------------
// Launch
// ---------------------------------------------------------------------------
extern "C" void kernel_launch(void* const* d_in, const int* in_sizes, int n_in,
                              void* d_out, int out_size)
{
    const float* xs = (const float*)d_in[0];
    const float* xq = (const float*)d_in[1];
    const float* W  = (const float*)d_in[2];
    float* out = (float*)d_out;

    float* z;        cudaGetSymbolAddress((void**)&z, g_z);
    float* protos;   cudaGetSymbolAddress((void**)&protos, g_protos);
    float* proto_sq; cudaGetSymbolAddress((void**)&proto_sq, g_proto_sq);
    float* qnorm;    cudaGetSymbolAddress((void**)&qnorm, g_qnorm);
    float* dists;    cudaGetSymbolAddress((void**)&dists, g_dists);
    float* lpart;    cudaGetSymbolAddress((void**)&lpart, g_lpart);
    float* apart;    cudaGetSymbolAddress((void**)&apart, g_apart);
    __nv_bfloat16 *A0, *A1, *A2, *WT0, *WT1, *WT2;
    __nv_bfloat16 *Zq0, *Zq1, *Zq2, *P0, *P1, *P2;
    cudaGetSymbolAddress((void**)&A0, g_A0);
    cudaGetSymbolAddress((void**)&A1, g_A1);
    cudaGetSymbolAddress((void**)&A2, g_A2);
    cudaGetSymbolAddress((void**)&WT0, g_WT0);
    cudaGetSymbolAddress((void**)&WT1, g_WT1);
    cudaGetSymbolAddress((void**)&WT2, g_WT2);
    cudaGetSymbolAddress((void**)&Zq0, g_Zq0);
    cudaGetSymbolAddress((void**)&Zq1, g_Zq1);
    cudaGetSymbolAddress((void**)&Zq2, g_Zq2);
    cudaGetSymbolAddress((void**)&P0, g_P0);
    cudaGetSymbolAddress((void**)&P1, g_P1);
    cudaGetSymbolAddress((void**)&P2, g_P2);

    float* zq = z + (size_t)NS_ROWS * Z_DIM;

    cudaFuncSetAttribute(gemm6_kernel<IN_DIM, 0>,
                         cudaFuncAttributeMaxDynamicSharedMemorySize, GT_SMEM);
    cudaFuncSetAttribute(gemm6_kernel<Z_DIM, 1>,
                         cudaFuncAttributeMaxDynamicSharedMemorySize, GT_SMEM);

    // 1) Split inputs into bf16 triples
    int nxs = NS_ROWS * IN_DIM;
    int nxq = NQ_ROWS * IN_DIM;
    size_t offq = (size_t)NS_ROWS * IN_DIM;
    split_a_kernel<<<nxs / 4 / 256, 256>>>(xs, A0, A1, A2, nxs);
    split_a_kernel<<<nxq / 4 / 256, 256>>>(xq, A0 + offq, A1 + offq, A2 + offq, nxq);
    split_wt_kernel<<<dim3(Z_DIM / 32, IN_DIM / 32), 256>>>(W, WT0, WT1, WT2);

    // 2) Projection GEMM (HMMA bf16x6, fp32 accumulate)
    gemm6_kernel<IN_DIM, 0><<<dim3(Z_DIM / 128, NZ_ROWS / 128), 256, GT_SMEM>>>(
        A0, A1, A2, WT0, WT1, WT2, z, nullptr, nullptr);

    // 3) zq splits + norms; centroids (protos row-major) + proto norms
    split_zq_norm_kernel<<<NQ_ROWS, 256>>>(zq, Zq0, Zq1, Zq2, qnorm);
    centroid_kernel<<<N_CLASS, 256>>>(z, protos, proto_sq);
    split_a_kernel<<<N_PROTO * Z_DIM / 4 / 256, 256>>>(protos, P0, P1, P2,
                                                       N_PROTO * Z_DIM);

    // 4) Query-proto distances (HMMA bf16x6 + dist epilogue)
    gemm6_kernel<Z_DIM, 1><<<dim3(N_PROTO / 128, NQ_ROWS / 128), 256, GT_SMEM>>>(
        Zq0, Zq1, Zq2, P0, P1, P2, dists, qnorm, proto_sq);

    // 5) Loss / acc
    loss_kernel<<<NQ_ROWS, 128>>>(dists, lpart, apart);
    final_kernel<<<1, 256>>>(lpart, apart, out);
}